// round 3
// baseline (speedup 1.0000x reference)
#include <cuda_runtime.h>
#include <math.h>

#define BB    2
#define HH    360
#define WG    360
#define HW    (HH*WG)          // 129600
#define NCLS  10
#define NPROP 200
#define CC    128
#define NPTS  80000
#define NBUCK 65536
#define MAXC  400000
#define SEL_CAP 2048

// output layout: qf (B,C,P) | query_pos (B,P,2) | qhs (B,NCLS,P) | cls (B,P)
#define OFF_QF  0
#define OFF_POS (BB*CC*NPROP)            // 51200
#define OFF_QHS (OFF_POS + BB*NPROP*2)   // 52000
#define OFF_CLS (OFF_QHS + BB*NCLS*NPROP)// 56000

// ---------------- scratch (device globals; re-initialized every launch) ----
__device__ float g_heat[BB*NCLS*HW];     // raw sigmoid heat, dense
__device__ float g_supp[BB*NCLS*HW];     // suppressed heat, dense
__device__ int   g_map [BB*HW];          // cell -> point row (-1 empty)
__device__ unsigned long long g_cand[BB*MAXC];
__device__ int   g_cnt[BB];
__device__ unsigned int g_hist[BB*NBUCK];
__device__ int   g_thr[BB];
__device__ int   g_selcnt[BB];
__device__ unsigned long long g_sel[BB*SEL_CAP];
__device__ unsigned long long g_top[BB*NPROP];

// ---------------- init: zero / reset all scratch ---------------------------
__global__ void init_kernel() {
    int stride = gridDim.x * blockDim.x;
    int i0 = blockIdx.x * blockDim.x + threadIdx.x;
    for (int j = i0; j < BB*NCLS*HW; j += stride) { g_heat[j] = 0.f; g_supp[j] = 0.f; }
    for (int j = i0; j < BB*HW;      j += stride) g_map[j] = -1;
    for (int j = i0; j < BB*NBUCK;   j += stride) g_hist[j] = 0u;
    if (i0 < BB) { g_cnt[i0] = 0; g_selcnt[i0] = 0; }
}

// ---------------- fused MLP head: hm = relu(F@W1+b1)@W2+b2 -> sigmoid -> scatter
// block: 256 threads, 128 rows x 128 cols tile; W1 resident in smem.
// dyn smem (floats): [0,16384) W1 | [16384,20608) A(32x132) | reuse [0,16896) H(128x132) | [20608,21888) W2
#define SMEM_FLOATS 21888
__global__ void __launch_bounds__(256, 2)
gemm_kernel(const float* __restrict__ feat, const float* __restrict__ W1,
            const float* __restrict__ b1,  const float* __restrict__ W2,
            const float* __restrict__ b2,  const int* __restrict__ idxs)
{
    extern __shared__ float sm[];
    float* sW1 = sm;                 // 128*128
    float* sA  = sm + 16384;         // 32*132
    float* sH  = sm;                 // 128*132 (reuses W1+A after phase 1)
    float* sW2 = sm + 20608;         // 128*10

    const int tid = threadIdx.x;
    const int rowBase = blockIdx.x * 128;

    for (int i = tid*4; i < CC*CC; i += 256*4)
        *(float4*)(sW1 + i) = *(const float4*)(W1 + i);
    for (int i = tid; i < CC*NCLS; i += 256)
        sW2[i] = W2[i];

    const int tn = tid & 15, tm = tid >> 4;
    int cols[8];
#pragma unroll
    for (int j = 0; j < 8; j++)
        cols[j] = (j < 4) ? (tn*4 + j) : (64 + tn*4 + j - 4);

    float acc[8][8];
#pragma unroll
    for (int j = 0; j < 8; j++) {
        float bj = b1[cols[j]];
#pragma unroll
        for (int i = 0; i < 8; i++) acc[i][j] = bj;
    }
    __syncthreads();   // W1/W2 visible

    const int lrow = tid >> 3;          // 0..31
    const int lk4  = (tid & 7) * 4;     // 0..28
    for (int kc = 0; kc < 4; kc++) {
#pragma unroll
        for (int pass = 0; pass < 4; pass++) {
            int r = lrow + pass*32;
            float4 v = *(const float4*)(feat + (size_t)(rowBase + r)*CC + kc*32 + lk4);
            sA[(lk4+0)*132 + r] = v.x;
            sA[(lk4+1)*132 + r] = v.y;
            sA[(lk4+2)*132 + r] = v.z;
            sA[(lk4+3)*132 + r] = v.w;
        }
        __syncthreads();
#pragma unroll 4
        for (int k = 0; k < 32; k++) {
            float a[8], bb[8];
            *(float4*)(a)    = *(float4*)(sA + k*132 + tm*8);
            *(float4*)(a+4)  = *(float4*)(sA + k*132 + tm*8 + 4);
            *(float4*)(bb)   = *(float4*)(sW1 + (kc*32+k)*128 + tn*4);
            *(float4*)(bb+4) = *(float4*)(sW1 + (kc*32+k)*128 + 64 + tn*4);
#pragma unroll
            for (int i = 0; i < 8; i++)
#pragma unroll
                for (int j = 0; j < 8; j++)
                    acc[i][j] = fmaf(a[i], bb[j], acc[i][j]);
        }
        __syncthreads();
    }

    // relu -> sH
#pragma unroll
    for (int i = 0; i < 8; i++) {
        int r = tm*8 + i;
#pragma unroll
        for (int j = 0; j < 8; j++)
            sH[r*132 + cols[j]] = fmaxf(acc[i][j], 0.f);
    }
    __syncthreads();

    // phase 2: hm = H @ W2 + b2, sigmoid, scatter
    const int r   = tid & 127;
    const int grp = tid >> 7;      // 0 -> cls 0..4, 1 -> cls 5..9
    float o[5];
#pragma unroll
    for (int i = 0; i < 5; i++) o[i] = b2[grp*5 + i];
    for (int j = 0; j < 128; j++) {
        float a = sH[r*132 + j];
#pragma unroll
        for (int i = 0; i < 5; i++)
            o[i] = fmaf(a, sW2[j*NCLS + grp*5 + i], o[i]);
    }
    const int gr = rowBase + r;
    const int bi = idxs[gr*3], yi = idxs[gr*3+1], xi = idxs[gr*3+2];
    const int cell = yi*WG + xi;
#pragma unroll
    for (int i = 0; i < 5; i++) {
        int c = grp*5 + i;
        float heat = 1.f / (1.f + expf(-o[i]));
        g_heat[(bi*NCLS + c)*HW + cell] = heat;
    }
    if (grp == 0) g_map[bi*HW + cell] = gr;
}

// ---------------- NMS + candidate push + histogram -------------------------
__global__ void nms_kernel() {
    int gid = blockIdx.x * blockDim.x + threadIdx.x;   // over B*HW
    if (gid >= BB*HW) return;
    if (g_map[gid] < 0) return;                        // empty cell: supp stays 0
    int b = gid / HW, cell = gid - b*HW;
    int y = cell / WG, x = cell - y*WG;
    bool inner = (y > 0) & (y < HH-1) & (x > 0) & (x < WG-1);
    const float* hb = g_heat + (size_t)b*NCLS*HW;
    for (int c = 0; c < NCLS; c++) {
        const float* hc = hb + c*HW;
        float ctr = hc[cell];
        float s;
        if (c >= 8) {
            s = ctr;
        } else if (!inner) {
            s = 0.f;   // border: local_max==0, heat>0 -> suppressed
        } else {
            bool keep = (ctr >= hc[cell-WG-1]) & (ctr >= hc[cell-WG]) & (ctr >= hc[cell-WG+1])
                      & (ctr >= hc[cell-1])                           & (ctr >= hc[cell+1])
                      & (ctr >= hc[cell+WG-1]) & (ctr >= hc[cell+WG]) & (ctr >= hc[cell+WG+1]);
            s = keep ? ctr : 0.f;
        }
        if (s > 0.f) {
            g_supp[((size_t)b*NCLS + c)*HW + cell] = s;
            unsigned key = (unsigned)(c*HW + cell);
            unsigned vb  = __float_as_uint(s);  // positive float: bit order == value order
            unsigned long long sk = ((unsigned long long)vb << 32)
                                  | (unsigned long long)(0xFFFFFFFFu - key);
            int p = atomicAdd(&g_cnt[b], 1);
            if (p < MAXC) g_cand[(size_t)b*MAXC + p] = sk;
            atomicAdd(&g_hist[b*NBUCK + (vb >> 16)], 1u);
        }
    }
}

// ---------------- find per-batch threshold bucket containing rank-200 ------
__global__ void thresh_kernel() {
    __shared__ unsigned csum[1024];
    for (int b = 0; b < BB; b++) {
        const unsigned* h = g_hist + b*NBUCK;
        unsigned t = threadIdx.x, s = 0;
        for (int i = 0; i < 64; i++) s += h[t*64 + i];
        csum[t] = s;
        __syncthreads();
        if (t == 0) {
            unsigned acc = 0; int chunk = 1023; unsigned above = 0;
            for (int ci = 1023; ci >= 0; ci--) {
                if (acc + csum[ci] >= NPROP) { chunk = ci; above = acc; break; }
                acc += csum[ci];
            }
            int T = chunk*64;
            unsigned a2 = above;
            for (int i = 63; i >= 0; i--) {
                unsigned cc = h[chunk*64 + i];
                if (a2 + cc >= NPROP) { T = chunk*64 + i; break; }
                a2 += cc;
            }
            g_thr[b] = T;
        }
        __syncthreads();
    }
}

// ---------------- gather candidates >= threshold bucket --------------------
__global__ void gather_kernel() {
    int gid = blockIdx.x * blockDim.x + threadIdx.x;  // over B*MAXC
    if (gid >= BB*MAXC) return;
    int b = gid / MAXC, i = gid - b*MAXC;
    int n = g_cnt[b]; if (n > MAXC) n = MAXC;
    if (i >= n) return;
    unsigned long long sk = g_cand[(size_t)b*MAXC + i];
    if ((int)(sk >> 48) >= g_thr[b]) {
        int p = atomicAdd(&g_selcnt[b], 1);
        if (p < SEL_CAP) g_sel[b*SEL_CAP + p] = sk;
    }
}

// ---------------- exact rank of the small selected set ---------------------
__global__ void rank_kernel() {
    __shared__ unsigned long long sk[SEL_CAP];
    int b = blockIdx.x;
    int M = g_selcnt[b]; if (M > SEL_CAP) M = SEL_CAP;
    for (int i = threadIdx.x; i < M; i += blockDim.x) sk[i] = g_sel[b*SEL_CAP + i];
    __syncthreads();
    for (int i = threadIdx.x; i < M; i += blockDim.x) {
        unsigned long long v = sk[i];
        int r = 0;
        for (int j = 0; j < M; j++) r += (sk[j] > v);
        if (r < NPROP) g_top[b*NPROP + r] = v;
    }
}

// ---------------- assemble outputs ------------------------------------------
__global__ void out_kernel(const float* __restrict__ feat,
                           const float* __restrict__ Wcls,
                           const float* __restrict__ bcls,
                           float* __restrict__ out)
{
    int b = blockIdx.x / NPROP, p = blockIdx.x - b*NPROP;
    unsigned long long sk = g_top[b*NPROP + p];
    unsigned key = 0xFFFFFFFFu - (unsigned)(sk & 0xFFFFFFFFu);
    int cls = key / HW, idx = key - cls*HW;
    int c = threadIdx.x;
    int row = g_map[b*HW + idx];
    float f = (row >= 0) ? feat[(size_t)row*CC + c] : 0.f;
    out[OFF_QF + (b*CC + c)*NPROP + p] = f + Wcls[c*NCLS + cls] + bcls[c];
    if (c < NCLS)
        out[OFF_QHS + (b*NCLS + c)*NPROP + p] = g_supp[((size_t)b*NCLS + c)*HW + idx];
    if (c == 0) {
        out[OFF_POS + (b*NPROP + p)*2 + 0] = (float)(idx % WG);
        out[OFF_POS + (b*NPROP + p)*2 + 1] = (float)(idx / WG);
        out[OFF_CLS + b*NPROP + p] = (float)cls;
    }
}

// ---------------- launch ----------------------------------------------------
extern "C" void kernel_launch(void* const* d_in, const int* in_sizes, int n_in,
                              void* d_out, int out_size)
{
    const float* feat = (const float*)d_in[0];
    const float* W1   = (const float*)d_in[1];
    const float* b1   = (const float*)d_in[2];
    const float* W2   = (const float*)d_in[3];
    const float* b2   = (const float*)d_in[4];
    const float* Wcls = (const float*)d_in[5];
    const float* bcls = (const float*)d_in[6];
    const int*   idxs = (const int*)d_in[7];
    float* out = (float*)d_out;

    cudaFuncSetAttribute(gemm_kernel, cudaFuncAttributeMaxDynamicSharedMemorySize,
                         SMEM_FLOATS * (int)sizeof(float));

    init_kernel<<<2048, 256>>>();
    gemm_kernel<<<NPTS/128, 256, SMEM_FLOATS * sizeof(float)>>>(feat, W1, b1, W2, b2, idxs);
    nms_kernel<<<(BB*HW + 255)/256, 256>>>();
    thresh_kernel<<<1, 1024>>>();
    gather_kernel<<<(BB*MAXC + 255)/256, 256>>>();
    rank_kernel<<<BB, 1024>>>();
    out_kernel<<<BB*NPROP, CC>>>(feat, Wcls, bcls, out);
}

// round 6
// speedup vs baseline: 3.0919x; 3.0919x over previous
#include <cuda_runtime.h>
#include <math.h>

#define BB    2
#define HH    360
#define WG    360
#define HW    (HH*WG)          // 129600
#define NCLS  10
#define NPROP 200
#define CC    128
#define NPTS  80000
#define NBUCK 65536
#define SEL_CAP 2048

// output layout: qf (B,C,P) | query_pos (B,P,2) | qhs (B,NCLS,P) | cls (B,P)
#define OFF_QF  0
#define OFF_POS (BB*CC*NPROP)            // 51200
#define OFF_QHS (OFF_POS + BB*NPROP*2)   // 52000
#define OFF_CLS (OFF_QHS + BB*NCLS*NPROP)// 56000

// ---------------- scratch (device globals; re-initialized every launch) ----
__device__ float g_heat[BB*NCLS*HW];     // raw sigmoid heat, dense
__device__ float g_supp[BB*NCLS*HW];     // suppressed heat, dense
__device__ int   g_map [BB*HW];          // cell -> point row (-1 empty)
__device__ unsigned int g_hist[BB*NBUCK];
__device__ int   g_thr[BB];
__device__ int   g_selcnt[BB];
__device__ unsigned long long g_sel[BB*SEL_CAP];
__device__ unsigned long long g_top[BB*NPROP];

// ---------------- packed f32x2 helpers -------------------------------------
__device__ __forceinline__ unsigned long long pk2(float lo, float hi) {
    unsigned long long r;
    asm("mov.b64 %0, {%1, %2};" : "=l"(r)
        : "r"(__float_as_uint(lo)), "r"(__float_as_uint(hi)));
    return r;
}
__device__ __forceinline__ unsigned long long pk1(float v) {
    unsigned long long r;
    asm("mov.b64 %0, {%1, %1};" : "=l"(r) : "r"(__float_as_uint(v)));
    return r;
}
__device__ __forceinline__ void upk(unsigned long long p, float& lo, float& hi) {
    unsigned a, b;
    asm("mov.b64 {%0, %1}, %2;" : "=r"(a), "=r"(b) : "l"(p));
    lo = __uint_as_float(a); hi = __uint_as_float(b);
}
__device__ __forceinline__ unsigned long long ffma2(unsigned long long a,
                                                    unsigned long long b,
                                                    unsigned long long c) {
    unsigned long long d;
    asm("fma.rn.f32x2 %0, %1, %2, %3;" : "=l"(d) : "l"(a), "l"(b), "l"(c));
    return d;
}

// ---------------- init: zero / reset all scratch ---------------------------
__global__ void init_kernel() {
    int stride = gridDim.x * blockDim.x;
    int i0 = blockIdx.x * blockDim.x + threadIdx.x;
    float4 z4 = make_float4(0.f, 0.f, 0.f, 0.f);
    for (int j = i0; j < BB*NCLS*HW/4; j += stride) {
        ((float4*)g_heat)[j] = z4;
        ((float4*)g_supp)[j] = z4;
    }
    int4 m4 = make_int4(-1, -1, -1, -1);
    for (int j = i0; j < BB*HW/4; j += stride) ((int4*)g_map)[j] = m4;
    uint4 zu = make_uint4(0u, 0u, 0u, 0u);
    for (int j = i0; j < BB*NBUCK/4; j += stride) ((uint4*)g_hist)[j] = zu;
    if (i0 < BB) g_selcnt[i0] = 0;
}

// ---------------- fused MLP head: hm = relu(F@W1+b1)@W2+b2 -> sigmoid -> scatter
// block: 256 threads, 128 rows x 128 cols tile; W1 resident in smem.
// Inner product done with packed fma.rn.f32x2 (2 FMAs/instr -> 2x FFMA rate).
// dyn smem (floats): [0,16384) W1 | [16384,20608) A(32x132) | reuse [0,16896) H(128x132) | [20608,21888) W2
#define SMEM_FLOATS 21888
__global__ void __launch_bounds__(256, 2)
gemm_kernel(const float* __restrict__ feat, const float* __restrict__ W1,
            const float* __restrict__ b1,  const float* __restrict__ W2,
            const float* __restrict__ b2,  const int* __restrict__ idxs)
{
    extern __shared__ float sm[];
    float* sW1 = sm;                 // 128*128
    float* sA  = sm + 16384;         // 32*132
    float* sH  = sm;                 // 128*132 (reuses W1+A after phase 1)
    float* sW2 = sm + 20608;         // 128*10

    const int tid = threadIdx.x;
    const int rowBase = blockIdx.x * 128;

    for (int i = tid*4; i < CC*CC; i += 256*4)
        *(float4*)(sW1 + i) = *(const float4*)(W1 + i);
    for (int i = tid; i < CC*NCLS; i += 256)
        sW2[i] = W2[i];

    const int tn = tid & 15, tm = tid >> 4;
    const int c0 = tn*4;          // cols c0..c0+3
    const int c1 = 64 + tn*4;     // cols c1..c1+3

    // acc pairs: [i][0]=(c0,c0+1) [i][1]=(c0+2,c0+3) [i][2]=(c1,c1+1) [i][3]=(c1+2,c1+3)
    unsigned long long acc2[8][4];
    {
        unsigned long long p0 = pk2(b1[c0],   b1[c0+1]);
        unsigned long long p1 = pk2(b1[c0+2], b1[c0+3]);
        unsigned long long p2 = pk2(b1[c1],   b1[c1+1]);
        unsigned long long p3 = pk2(b1[c1+2], b1[c1+3]);
#pragma unroll
        for (int i = 0; i < 8; i++) {
            acc2[i][0] = p0; acc2[i][1] = p1; acc2[i][2] = p2; acc2[i][3] = p3;
        }
    }
    __syncthreads();   // W1/W2 visible

    const int lrow = tid >> 3;          // 0..31
    const int lk4  = (tid & 7) * 4;     // 0..28
    for (int kc = 0; kc < 4; kc++) {
#pragma unroll
        for (int pass = 0; pass < 4; pass++) {
            int r = lrow + pass*32;
            float4 v = *(const float4*)(feat + (size_t)(rowBase + r)*CC + kc*32 + lk4);
            sA[(lk4+0)*132 + r] = v.x;
            sA[(lk4+1)*132 + r] = v.y;
            sA[(lk4+2)*132 + r] = v.z;
            sA[(lk4+3)*132 + r] = v.w;
        }
        __syncthreads();
#pragma unroll 4
        for (int k = 0; k < 32; k++) {
            float a[8];
            *(float4*)(a)    = *(float4*)(sA + k*132 + tm*8);
            *(float4*)(a+4)  = *(float4*)(sA + k*132 + tm*8 + 4);
            const unsigned long long* bw =
                (const unsigned long long*)(sW1 + (kc*32+k)*128);
            unsigned long long w0 = bw[tn*2];
            unsigned long long w1 = bw[tn*2 + 1];
            unsigned long long w2 = bw[32 + tn*2];
            unsigned long long w3 = bw[32 + tn*2 + 1];
#pragma unroll
            for (int i = 0; i < 8; i++) {
                unsigned long long aa = pk1(a[i]);
                acc2[i][0] = ffma2(aa, w0, acc2[i][0]);
                acc2[i][1] = ffma2(aa, w1, acc2[i][1]);
                acc2[i][2] = ffma2(aa, w2, acc2[i][2]);
                acc2[i][3] = ffma2(aa, w3, acc2[i][3]);
            }
        }
        __syncthreads();
    }

    // relu -> sH (packed 8B stores; offsets even -> aligned)
#pragma unroll
    for (int i = 0; i < 8; i++) {
        int r = tm*8 + i;
        float lo, hi;
        upk(acc2[i][0], lo, hi);
        *(unsigned long long*)(sH + r*132 + c0)     = pk2(fmaxf(lo,0.f), fmaxf(hi,0.f));
        upk(acc2[i][1], lo, hi);
        *(unsigned long long*)(sH + r*132 + c0 + 2) = pk2(fmaxf(lo,0.f), fmaxf(hi,0.f));
        upk(acc2[i][2], lo, hi);
        *(unsigned long long*)(sH + r*132 + c1)     = pk2(fmaxf(lo,0.f), fmaxf(hi,0.f));
        upk(acc2[i][3], lo, hi);
        *(unsigned long long*)(sH + r*132 + c1 + 2) = pk2(fmaxf(lo,0.f), fmaxf(hi,0.f));
    }
    __syncthreads();

    // phase 2: hm = H @ W2 + b2, sigmoid, scatter
    const int r   = tid & 127;
    const int grp = tid >> 7;      // 0 -> cls 0..4, 1 -> cls 5..9
    float o[5];
#pragma unroll
    for (int i = 0; i < 5; i++) o[i] = b2[grp*5 + i];
    for (int j = 0; j < 128; j++) {
        float a = sH[r*132 + j];
#pragma unroll
        for (int i = 0; i < 5; i++)
            o[i] = fmaf(a, sW2[j*NCLS + grp*5 + i], o[i]);
    }
    const int gr = rowBase + r;
    const int bi = idxs[gr*3], yi = idxs[gr*3+1], xi = idxs[gr*3+2];
    const int cell = yi*WG + xi;
#pragma unroll
    for (int i = 0; i < 5; i++) {
        int c = grp*5 + i;
        float heat = 1.f / (1.f + expf(-o[i]));
        g_heat[(bi*NCLS + c)*HW + cell] = heat;
    }
    if (grp == 0) g_map[bi*HW + cell] = gr;
}

// ---------------- NMS -> suppressed heat + histogram (NO candidate list) ---
__global__ void nms_kernel() {
    int gid = blockIdx.x * blockDim.x + threadIdx.x;   // over B*HW
    if (gid >= BB*HW) return;
    if (g_map[gid] < 0) return;                        // empty cell: supp stays 0
    int b = gid / HW, cell = gid - b*HW;
    int y = cell / WG, x = cell - y*WG;
    bool inner = (y > 0) & (y < HH-1) & (x > 0) & (x < WG-1);
    const float* hb = g_heat + (size_t)b*NCLS*HW;
    for (int c = 0; c < NCLS; c++) {
        const float* hc = hb + c*HW;
        float ctr = hc[cell];
        float s;
        if (c >= 8) {
            s = ctr;
        } else if (!inner) {
            s = 0.f;   // border: local_max==0, heat>0 -> suppressed
        } else {
            bool keep = (ctr >= hc[cell-WG-1]) & (ctr >= hc[cell-WG]) & (ctr >= hc[cell-WG+1])
                      & (ctr >= hc[cell-1])                           & (ctr >= hc[cell+1])
                      & (ctr >= hc[cell+WG-1]) & (ctr >= hc[cell+WG]) & (ctr >= hc[cell+WG+1]);
            s = keep ? ctr : 0.f;
        }
        if (s > 0.f) {
            g_supp[((size_t)b*NCLS + c)*HW + cell] = s;
            atomicAdd(&g_hist[b*NBUCK + (__float_as_uint(s) >> 16)], 1u);  // spread RED
        }
    }
}

// ---------------- per-batch threshold bucket containing rank-200 -----------
// one block per batch; uint4 loads + shared suffix scan (no serial thread-0 loop)
__global__ void thresh_kernel() {
    __shared__ unsigned sbuf[2][1024];
    int b = blockIdx.x;
    const unsigned* h = g_hist + b*NBUCK;
    int t = threadIdx.x;

    unsigned s = 0;
    const uint4* hv = (const uint4*)(h + t*64);
#pragma unroll
    for (int i = 0; i < 16; i++) {
        uint4 v = hv[i];
        s += v.x + v.y + v.z + v.w;
    }
    sbuf[0][t] = s;
    __syncthreads();

    // inclusive suffix scan: S[t] = sum_{t' >= t}
    int cur = 0;
    for (int off = 1; off < 1024; off <<= 1) {
        unsigned v = sbuf[cur][t] + ((t + off < 1024) ? sbuf[cur][t + off] : 0u);
        sbuf[cur ^ 1][t] = v;
        __syncthreads();
        cur ^= 1;
    }
    unsigned S_t  = sbuf[cur][t];
    unsigned S_t1 = (t < 1023) ? sbuf[cur][t + 1] : 0u;

    if (S_t >= NPROP && S_t1 < NPROP) {     // exactly one thread
        unsigned acc = S_t1;
        int T = t*64;
        for (int i = 63; i >= 0; i--) {
            unsigned c = h[t*64 + i];       // L1 hot
            if (acc + c >= NPROP) { T = t*64 + i; break; }
            acc += c;
        }
        g_thr[b] = T;
    }
}

// ---------------- gather candidates >= threshold from DENSE supp -----------
// index j within a batch's dense (NCLS*HW) block IS the top-k key.
__global__ void gather_kernel() {
    const int N4 = BB*NCLS*HW/4;
    int gid = blockIdx.x * blockDim.x + threadIdx.x;
    if (gid >= N4) return;
    float4 v = ((const float4*)g_supp)[gid];
    int base = gid * 4;
    int b = base / (NCLS*HW);
    int T = g_thr[b];
    float vv[4] = {v.x, v.y, v.z, v.w};
#pragma unroll
    for (int u = 0; u < 4; u++) {
        unsigned vb = __float_as_uint(vv[u]);
        if ((int)(vb >> 16) >= T) {
            unsigned j = (unsigned)(base + u - b*NCLS*HW);   // key = c*HW + cell
            unsigned long long sk = ((unsigned long long)vb << 32)
                                  | (unsigned long long)(0xFFFFFFFFu - j);
            int p = atomicAdd(&g_selcnt[b], 1);              // ~250 ops/batch
            if (p < SEL_CAP) g_sel[b*SEL_CAP + p] = sk;
        }
    }
}

// ---------------- exact rank of the small selected set ---------------------
__global__ void rank_kernel() {
    __shared__ unsigned long long sk[SEL_CAP];
    int b = blockIdx.x;
    int M = g_selcnt[b]; if (M > SEL_CAP) M = SEL_CAP;
    for (int i = threadIdx.x; i < M; i += blockDim.x) sk[i] = g_sel[b*SEL_CAP + i];
    __syncthreads();
    for (int i = threadIdx.x; i < M; i += blockDim.x) {
        unsigned long long v = sk[i];
        int r = 0;
        for (int j = 0; j < M; j++) r += (sk[j] > v);
        if (r < NPROP) g_top[b*NPROP + r] = v;
    }
}

// ---------------- assemble outputs ------------------------------------------
__global__ void out_kernel(const float* __restrict__ feat,
                           const float* __restrict__ Wcls,
                           const float* __restrict__ bcls,
                           float* __restrict__ out)
{
    int b = blockIdx.x / NPROP, p = blockIdx.x - b*NPROP;
    unsigned long long sk = g_top[b*NPROP + p];
    unsigned key = 0xFFFFFFFFu - (unsigned)(sk & 0xFFFFFFFFu);
    int cls = key / HW, idx = key - cls*HW;
    int c = threadIdx.x;
    int row = g_map[b*HW + idx];
    float f = (row >= 0) ? feat[(size_t)row*CC + c] : 0.f;
    out[OFF_QF + (b*CC + c)*NPROP + p] = f + Wcls[c*NCLS + cls] + bcls[c];
    if (c < NCLS)
        out[OFF_QHS + (b*NCLS + c)*NPROP + p] = g_supp[((size_t)b*NCLS + c)*HW + idx];
    if (c == 0) {
        out[OFF_POS + (b*NPROP + p)*2 + 0] = (float)(idx % WG);
        out[OFF_POS + (b*NPROP + p)*2 + 1] = (float)(idx / WG);
        out[OFF_CLS + b*NPROP + p] = (float)cls;
    }
}

// ---------------- launch ----------------------------------------------------
extern "C" void kernel_launch(void* const* d_in, const int* in_sizes, int n_in,
                              void* d_out, int out_size)
{
    const float* feat = (const float*)d_in[0];
    const float* W1   = (const float*)d_in[1];
    const float* b1   = (const float*)d_in[2];
    const float* W2   = (const float*)d_in[3];
    const float* b2   = (const float*)d_in[4];
    const float* Wcls = (const float*)d_in[5];
    const float* bcls = (const float*)d_in[6];
    const int*   idxs = (const int*)d_in[7];
    float* out = (float*)d_out;

    cudaFuncSetAttribute(gemm_kernel, cudaFuncAttributeMaxDynamicSharedMemorySize,
                         SMEM_FLOATS * (int)sizeof(float));

    init_kernel<<<2048, 256>>>();
    gemm_kernel<<<NPTS/128, 256, SMEM_FLOATS * sizeof(float)>>>(feat, W1, b1, W2, b2, idxs);
    nms_kernel<<<(BB*HW + 255)/256, 256>>>();
    thresh_kernel<<<BB, 1024>>>();
    gather_kernel<<<(BB*NCLS*HW/4 + 255)/256, 256>>>();
    rank_kernel<<<BB, 1024>>>();
    out_kernel<<<BB*NPROP, CC>>>(feat, Wcls, bcls, out);
}